// round 1
// baseline (speedup 1.0000x reference)
#include <cuda_runtime.h>
#include <cstdint>

#define NAG   4096
#define TOPK  12
#define NITEMS (NAG * TOPK)      // 49152
#define T1    256                // threads, topk kernel
#define EPT   16                 // elements per thread = 4096/256
#define LSTR  13                 // padded list stride (bank-conflict avoidance)
#define T2    128                // threads, mlp kernel

__device__ int g_topk_idx[NITEMS];

// ---------------------------------------------------------------------------
// Kernel 1: per-row top-12 by dn = sqrt((x0^2+1e-6)+(x1^2+1e-6)), ties by j.
// Key = (float_bits(dn) << 32) | j  -> single u64 compare replicates jax
// lax.top_k ordering exactly (dn >= sqrt(2e-6) > 0 so bits are monotone).
// ---------------------------------------------------------------------------
__global__ void __launch_bounds__(T1) topk_kernel(const float* __restrict__ x) {
    const int i   = blockIdx.x;
    const int tid = threadIdx.x;
    const float* row = x + (size_t)i * (NAG * 4);

    unsigned long long keys[EPT];
#pragma unroll
    for (int t = 0; t < EPT; ++t) {
        const int j = tid + t * T1;
        const float2 v = *reinterpret_cast<const float2*>(row + (size_t)j * 4);
        // replicate reference bitwise: (x0*x0 + 1e-6) + (x1*x1 + 1e-6), no FMA
        const float s = __fadd_rn(__fadd_rn(__fmul_rn(v.x, v.x), 1e-6f),
                                  __fadd_rn(__fmul_rn(v.y, v.y), 1e-6f));
        const float dn = __fsqrt_rn(s);
        keys[t] = ((unsigned long long)__float_as_uint(dn) << 32) | (unsigned)j;
    }

    // fully-unrolled bitonic sort of 16 keys, ascending, stays in registers
#pragma unroll
    for (int kk = 2; kk <= EPT; kk <<= 1) {
#pragma unroll
        for (int jj = kk >> 1; jj > 0; jj >>= 1) {
#pragma unroll
            for (int ii = 0; ii < EPT; ++ii) {
                const int ll = ii ^ jj;
                if (ll > ii) {
                    const bool up = ((ii & kk) == 0);
                    const unsigned long long a = keys[ii];
                    const unsigned long long b = keys[ll];
                    const bool sw = up ? (a > b) : (a < b);
                    if (sw) { keys[ii] = b; keys[ll] = a; }
                }
            }
        }
    }

    __shared__ unsigned long long skeys[T1 * LSTR];
#pragma unroll
    for (int t = 0; t < TOPK; ++t) skeys[tid * LSTR + t] = keys[t];

    __shared__ unsigned long long swarp[T1 / 32];
    __shared__ unsigned long long sbcast;
    __syncthreads();

    // 12-way merge of 256 sorted lists: each pass = block argmin over heads.
    int head = 0;
#pragma unroll 1
    for (int pass = 0; pass < TOPK; ++pass) {
        const unsigned long long mykey =
            (head < TOPK) ? skeys[tid * LSTR + head] : 0xFFFFFFFFFFFFFFFFULL;
        unsigned long long v = mykey;
#pragma unroll
        for (int off = 16; off > 0; off >>= 1) {
            const unsigned long long o = __shfl_down_sync(0xffffffffu, v, off);
            v = (o < v) ? o : v;
        }
        if ((tid & 31) == 0) swarp[tid >> 5] = v;
        __syncthreads();
        if (tid == 0) {
            unsigned long long m = swarp[0];
#pragma unroll
            for (int w = 1; w < T1 / 32; ++w) m = (swarp[w] < m) ? swarp[w] : m;
            sbcast = m;
            g_topk_idx[i * TOPK + pass] = (int)(unsigned)(m & 0xFFFFFFFFULL);
        }
        __syncthreads();
        if (mykey == sbcast) head++;   // keys unique (low bits = j) -> exactly one
    }
}

// ---------------------------------------------------------------------------
// Kernel 2: one thread per (agent, k) item: gather features, run MLP
// 6 -> 64 -> 128 -> 64 -> 1 (relu between), write out/mask/indices.
// Weights: W1/biases/W4 + transposed W3 in static smem (broadcast LDS);
// W2 rows read as uniform LDG.128 (L1 broadcast).
// ---------------------------------------------------------------------------
__global__ void __launch_bounds__(T2) mlp_kernel(
    const float* __restrict__ x,  const float* __restrict__ rp,
    const float* __restrict__ W1, const float* __restrict__ b1,
    const float* __restrict__ W2, const float* __restrict__ b2,
    const float* __restrict__ W3, const float* __restrict__ b3,
    const float* __restrict__ W4, const float* __restrict__ b4,
    float* __restrict__ out)
{
    __shared__ float W3ts[128 * 64];   // W3 transposed: [m][o]
    __shared__ float W1s[64 * 6];
    __shared__ float b1s[64];
    __shared__ float b2s[128];
    __shared__ float b3s[64];
    __shared__ float W4s[64];

    const int tid = threadIdx.x;
    for (int s = tid; s < 8192; s += T2) {
        const int o = s >> 7, m = s & 127;
        W3ts[m * 64 + o] = W3[s];
    }
    for (int s = tid; s < 384; s += T2) W1s[s] = W1[s];
    if (tid < 64)  b1s[tid] = b1[tid];
    if (tid < 128) b2s[tid] = b2[tid];
    if (tid < 64)  b3s[tid] = b3[tid];
    if (tid < 64)  W4s[tid] = W4[tid];
    __syncthreads();

    const int item = blockIdx.x * T2 + tid;
    const int i = item / TOPK;
    const int j = g_topk_idx[item];

    const float4 v = *reinterpret_cast<const float4*>(x + ((size_t)i * NAG + (size_t)j) * 4);
    // replicate reference bitwise: sqrt((x0^2+1e-4)+(x1^2+1e-4))
    const float s2 = __fadd_rn(__fadd_rn(__fmul_rn(v.x, v.x), 1e-4f),
                               __fadd_rn(__fmul_rn(v.y, v.y), 1e-4f));
    const float dn = __fsqrt_rn(s2);
    const float r  = rp[0];
    const float mask = (dn <= 1.0f) ? 1.0f : 0.0f;
    const float f0 = v.x, f1 = v.y, f2 = v.z, f3 = v.w;
    const float f4 = (i == j) ? 1.0f : 0.0f;
    const float f5 = dn - r;

    // layer 1: 6 -> 64
    float h1[64];
#pragma unroll
    for (int o = 0; o < 64; ++o) {
        const float* w = W1s + o * 6;
        float a = b1s[o];
        a = fmaf(w[0], f0, a); a = fmaf(w[1], f1, a); a = fmaf(w[2], f2, a);
        a = fmaf(w[3], f3, a); a = fmaf(w[4], f4, a); a = fmaf(w[5], f5, a);
        h1[o] = fmaxf(a, 0.0f);
    }

    // layers 2+3 fused: h3[o] = relu(b3[o] + sum_m W3[o][m]*relu(b2[m] + W2[m]·h1))
    float acc[64];
#pragma unroll
    for (int o = 0; o < 64; ++o) acc[o] = b3s[o];

#pragma unroll 2
    for (int m = 0; m < 128; ++m) {
        const float4* w2 = reinterpret_cast<const float4*>(W2 + m * 64);
        float s0 = 0.f, s1 = 0.f, sa = 0.f, sb = 0.f;
#pragma unroll
        for (int c = 0; c < 16; ++c) {
            const float4 w = w2[c];
            s0 = fmaf(w.x, h1[4 * c + 0], s0);
            s1 = fmaf(w.y, h1[4 * c + 1], s1);
            sa = fmaf(w.z, h1[4 * c + 2], sa);
            sb = fmaf(w.w, h1[4 * c + 3], sb);
        }
        const float t = fmaxf((s0 + s1) + (sa + sb) + b2s[m], 0.0f);
        const float4* w3 = reinterpret_cast<const float4*>(W3ts + m * 64);
#pragma unroll
        for (int c = 0; c < 16; ++c) {
            const float4 w = w3[c];
            acc[4 * c + 0] = fmaf(w.x, t, acc[4 * c + 0]);
            acc[4 * c + 1] = fmaf(w.y, t, acc[4 * c + 1]);
            acc[4 * c + 2] = fmaf(w.z, t, acc[4 * c + 2]);
            acc[4 * c + 3] = fmaf(w.w, t, acc[4 * c + 3]);
        }
    }

    // layer 4: 64 -> 1
    float o0 = 0.f, o1 = 0.f, o2 = 0.f, o3 = 0.f;
#pragma unroll
    for (int c = 0; c < 16; ++c) {
        o0 = fmaf(W4s[4 * c + 0], fmaxf(acc[4 * c + 0], 0.f), o0);
        o1 = fmaf(W4s[4 * c + 1], fmaxf(acc[4 * c + 1], 0.f), o1);
        o2 = fmaf(W4s[4 * c + 2], fmaxf(acc[4 * c + 2], 0.f), o2);
        o3 = fmaf(W4s[4 * c + 3], fmaxf(acc[4 * c + 3], 0.f), o3);
    }
    const float res = (((o0 + o1) + (o2 + o3)) + b4[0]) * mask;

    // outputs: [out | mask | indices] flattened fp32
    out[item] = res;
    out[NITEMS + item] = mask;
    out[2 * NITEMS + 2 * item + 0] = (float)i;
    out[2 * NITEMS + 2 * item + 1] = (float)j;
}

extern "C" void kernel_launch(void* const* d_in, const int* in_sizes, int n_in,
                              void* d_out, int out_size) {
    const float* x  = (const float*)d_in[0];
    const float* r  = (const float*)d_in[1];
    const float* W1 = (const float*)d_in[2];
    const float* b1 = (const float*)d_in[3];
    const float* W2 = (const float*)d_in[4];
    const float* b2 = (const float*)d_in[5];
    const float* W3 = (const float*)d_in[6];
    const float* b3 = (const float*)d_in[7];
    const float* W4 = (const float*)d_in[8];
    const float* b4 = (const float*)d_in[9];
    float* out = (float*)d_out;

    topk_kernel<<<NAG, T1>>>(x);
    mlp_kernel<<<NITEMS / T2, T2>>>(x, r, W1, b1, W2, b2, W3, b3, W4, b4, out);
}

// round 2
// speedup vs baseline: 1.4385x; 1.4385x over previous
#include <cuda_runtime.h>
#include <cstdint>

#define NAG   4096
#define TOPK  12
#define NITEMS (NAG * TOPK)      // 49152
#define T1    256                // threads, topk kernel
#define EPT   16                 // elements per thread = 4096/256
#define LSTR  13                 // padded list stride

__device__ int   g_topk_idx[NITEMS];
__device__ float g_H1[64 * NITEMS];      // [k][item]  12.6 MB
__device__ float g_H2[128 * NITEMS];     // [k][item]  25.2 MB
__device__ float g_W2t[64 * 128];        // [k][m]
__device__ float g_W3t[128 * 64];        // [k][o]

// ---------------------------------------------------------------------------
// Kernel 1: per-row top-12 (unchanged from passing baseline)
// ---------------------------------------------------------------------------
__global__ void __launch_bounds__(T1) topk_kernel(const float* __restrict__ x) {
    const int i   = blockIdx.x;
    const int tid = threadIdx.x;
    const float* row = x + (size_t)i * (NAG * 4);

    unsigned long long keys[EPT];
#pragma unroll
    for (int t = 0; t < EPT; ++t) {
        const int j = tid + t * T1;
        const float2 v = *reinterpret_cast<const float2*>(row + (size_t)j * 4);
        const float s = __fadd_rn(__fadd_rn(__fmul_rn(v.x, v.x), 1e-6f),
                                  __fadd_rn(__fmul_rn(v.y, v.y), 1e-6f));
        const float dn = __fsqrt_rn(s);
        keys[t] = ((unsigned long long)__float_as_uint(dn) << 32) | (unsigned)j;
    }

#pragma unroll
    for (int kk = 2; kk <= EPT; kk <<= 1) {
#pragma unroll
        for (int jj = kk >> 1; jj > 0; jj >>= 1) {
#pragma unroll
            for (int ii = 0; ii < EPT; ++ii) {
                const int ll = ii ^ jj;
                if (ll > ii) {
                    const bool up = ((ii & kk) == 0);
                    const unsigned long long a = keys[ii];
                    const unsigned long long b = keys[ll];
                    const bool sw = up ? (a > b) : (a < b);
                    if (sw) { keys[ii] = b; keys[ll] = a; }
                }
            }
        }
    }

    __shared__ unsigned long long skeys[T1 * LSTR];
#pragma unroll
    for (int t = 0; t < TOPK; ++t) skeys[tid * LSTR + t] = keys[t];

    __shared__ unsigned long long swarp[T1 / 32];
    __shared__ unsigned long long sbcast;
    __syncthreads();

    int head = 0;
#pragma unroll 1
    for (int pass = 0; pass < TOPK; ++pass) {
        const unsigned long long mykey =
            (head < TOPK) ? skeys[tid * LSTR + head] : 0xFFFFFFFFFFFFFFFFULL;
        unsigned long long v = mykey;
#pragma unroll
        for (int off = 16; off > 0; off >>= 1) {
            const unsigned long long o = __shfl_down_sync(0xffffffffu, v, off);
            v = (o < v) ? o : v;
        }
        if ((tid & 31) == 0) swarp[tid >> 5] = v;
        __syncthreads();
        if (tid == 0) {
            unsigned long long m = swarp[0];
#pragma unroll
            for (int w = 1; w < T1 / 32; ++w) m = (swarp[w] < m) ? swarp[w] : m;
            sbcast = m;
            g_topk_idx[i * TOPK + pass] = (int)(unsigned)(m & 0xFFFFFFFFULL);
        }
        __syncthreads();
        if (mykey == sbcast) head++;
    }
}

// ---------------------------------------------------------------------------
// Kernel T: transpose W2 [128m][64k] -> W2t [64k][128m],
//           W3 [64o][128m] -> W3t [128m][64o]
// ---------------------------------------------------------------------------
__global__ void __launch_bounds__(256) transpose_kernel(
    const float* __restrict__ W2, const float* __restrict__ W3)
{
    const int tid = threadIdx.x;
    for (int s = tid; s < 128 * 64; s += 256) {
        const int m = s >> 6, k = s & 63;
        g_W2t[k * 128 + m] = W2[s];
    }
    for (int s = tid; s < 64 * 128; s += 256) {
        const int o = s >> 7, m = s & 127;
        g_W3t[m * 64 + o] = W3[s];
    }
}

// ---------------------------------------------------------------------------
// Kernel A: gather features + layer1 (6->64), write H1 transposed [k][item].
// Also writes mask and indices to out.
// ---------------------------------------------------------------------------
__global__ void __launch_bounds__(256) feat_kernel(
    const float* __restrict__ x,  const float* __restrict__ rp,
    const float* __restrict__ W1, const float* __restrict__ b1,
    float* __restrict__ out)
{
    __shared__ float W1s[64 * 6];
    __shared__ float b1s[64];
    const int tid = threadIdx.x;
    for (int s = tid; s < 384; s += 256) W1s[s] = W1[s];
    if (tid < 64) b1s[tid] = b1[tid];
    __syncthreads();

    const int item = blockIdx.x * 256 + tid;
    const int i = item / TOPK;
    const int j = g_topk_idx[item];

    const float4 v = *reinterpret_cast<const float4*>(x + ((size_t)i * NAG + (size_t)j) * 4);
    const float s2 = __fadd_rn(__fadd_rn(__fmul_rn(v.x, v.x), 1e-4f),
                               __fadd_rn(__fmul_rn(v.y, v.y), 1e-4f));
    const float dn = __fsqrt_rn(s2);
    const float r  = rp[0];
    const float mask = (dn <= 1.0f) ? 1.0f : 0.0f;
    const float f0 = v.x, f1 = v.y, f2 = v.z, f3 = v.w;
    const float f4 = (i == j) ? 1.0f : 0.0f;
    const float f5 = dn - r;

#pragma unroll
    for (int o = 0; o < 64; ++o) {
        const float* w = W1s + o * 6;
        float a = b1s[o];
        a = fmaf(w[0], f0, a); a = fmaf(w[1], f1, a); a = fmaf(w[2], f2, a);
        a = fmaf(w[3], f3, a); a = fmaf(w[4], f4, a); a = fmaf(w[5], f5, a);
        g_H1[o * NITEMS + item] = fmaxf(a, 0.0f);   // coalesced per-warp
    }

    out[NITEMS + item] = mask;
    out[2 * NITEMS + 2 * item + 0] = (float)i;
    out[2 * NITEMS + 2 * item + 1] = (float)j;
}

// ---------------------------------------------------------------------------
// Kernel B: GEMM1  H2[m][item] = relu(b2[m] + sum_k W2t[k][m] * H1[k][item])
// M=128, N=NITEMS, K=64. 256 threads/block, block = 128 items x 128 m,
// thread tile = 8m x 8items. All loads LDG.128 (L1-resident weights/tiles).
// ---------------------------------------------------------------------------
__global__ void __launch_bounds__(256) gemm1_kernel(const float* __restrict__ b2)
{
    const int tid = threadIdx.x;
    const int tm  = tid >> 4;            // 0..15 -> m tile
    const int ti  = tid & 15;            // 0..15 -> item tile
    const int m0  = tm * 8;
    const int it0 = blockIdx.x * 128 + ti * 8;

    float acc[8][8];
#pragma unroll
    for (int mm = 0; mm < 8; ++mm) {
        const float b = b2[m0 + mm];
#pragma unroll
        for (int ii = 0; ii < 8; ++ii) acc[mm][ii] = b;
    }

#pragma unroll 4
    for (int k = 0; k < 64; ++k) {
        const float4 a0 = *reinterpret_cast<const float4*>(g_W2t + k * 128 + m0);
        const float4 a1 = *reinterpret_cast<const float4*>(g_W2t + k * 128 + m0 + 4);
        const float4 x0 = *reinterpret_cast<const float4*>(g_H1 + (size_t)k * NITEMS + it0);
        const float4 x1 = *reinterpret_cast<const float4*>(g_H1 + (size_t)k * NITEMS + it0 + 4);
        const float av[8] = {a0.x, a0.y, a0.z, a0.w, a1.x, a1.y, a1.z, a1.w};
        const float xv[8] = {x0.x, x0.y, x0.z, x0.w, x1.x, x1.y, x1.z, x1.w};
#pragma unroll
        for (int mm = 0; mm < 8; ++mm)
#pragma unroll
            for (int ii = 0; ii < 8; ++ii)
                acc[mm][ii] = fmaf(av[mm], xv[ii], acc[mm][ii]);
    }

#pragma unroll
    for (int mm = 0; mm < 8; ++mm) {
        float4 s0, s1;
        s0.x = fmaxf(acc[mm][0], 0.f); s0.y = fmaxf(acc[mm][1], 0.f);
        s0.z = fmaxf(acc[mm][2], 0.f); s0.w = fmaxf(acc[mm][3], 0.f);
        s1.x = fmaxf(acc[mm][4], 0.f); s1.y = fmaxf(acc[mm][5], 0.f);
        s1.z = fmaxf(acc[mm][6], 0.f); s1.w = fmaxf(acc[mm][7], 0.f);
        *reinterpret_cast<float4*>(g_H2 + (size_t)(m0 + mm) * NITEMS + it0)     = s0;
        *reinterpret_cast<float4*>(g_H2 + (size_t)(m0 + mm) * NITEMS + it0 + 4) = s1;
    }
}

// ---------------------------------------------------------------------------
// Kernel C: GEMM2  h3[o][item] = relu(b3[o] + sum_k W3t[k][o] * H2[k][item])
// fused layer4: out[item] = (sum_o W4[o]*h3[o][item] + b4) * mask
// M=64, N=NITEMS, K=128. 128 threads/block, block = 128 items x 64 o,
// thread tile = 8o x 8items, 8-way smem reduction for the W4 dot.
// ---------------------------------------------------------------------------
__global__ void __launch_bounds__(128) gemm2_kernel(
    const float* __restrict__ b3, const float* __restrict__ W4,
    const float* __restrict__ b4, float* __restrict__ out)
{
    const int tid = threadIdx.x;
    const int to  = tid >> 4;            // 0..7  -> o tile
    const int ti  = tid & 15;            // 0..15 -> item tile
    const int o0  = to * 8;
    const int it0 = blockIdx.x * 128 + ti * 8;

    float acc[8][8];
#pragma unroll
    for (int mm = 0; mm < 8; ++mm) {
        const float b = b3[o0 + mm];
#pragma unroll
        for (int ii = 0; ii < 8; ++ii) acc[mm][ii] = b;
    }

#pragma unroll 4
    for (int k = 0; k < 128; ++k) {
        const float4 a0 = *reinterpret_cast<const float4*>(g_W3t + k * 64 + o0);
        const float4 a1 = *reinterpret_cast<const float4*>(g_W3t + k * 64 + o0 + 4);
        const float4 x0 = *reinterpret_cast<const float4*>(g_H2 + (size_t)k * NITEMS + it0);
        const float4 x1 = *reinterpret_cast<const float4*>(g_H2 + (size_t)k * NITEMS + it0 + 4);
        const float av[8] = {a0.x, a0.y, a0.z, a0.w, a1.x, a1.y, a1.z, a1.w};
        const float xv[8] = {x0.x, x0.y, x0.z, x0.w, x1.x, x1.y, x1.z, x1.w};
#pragma unroll
        for (int mm = 0; mm < 8; ++mm)
#pragma unroll
            for (int ii = 0; ii < 8; ++ii)
                acc[mm][ii] = fmaf(av[mm], xv[ii], acc[mm][ii]);
    }

    // partial W4 dot over this thread's 8 o's, for its 8 items
    __shared__ float red[8][136];
    float w4v[8];
#pragma unroll
    for (int mm = 0; mm < 8; ++mm) w4v[mm] = W4[o0 + mm];

#pragma unroll
    for (int ii = 0; ii < 8; ++ii) {
        float p = 0.f;
#pragma unroll
        for (int mm = 0; mm < 8; ++mm)
            p = fmaf(w4v[mm], fmaxf(acc[mm][ii], 0.f), p);
        red[to][ti * 8 + ii] = p;
    }
    __syncthreads();

    // final reduction: one thread per item (128 threads, 128 items)
    const int item = blockIdx.x * 128 + tid;
    float s = red[0][tid];
#pragma unroll
    for (int g = 1; g < 8; ++g) s += red[g][tid];
    const float mask = out[NITEMS + item];        // written by feat_kernel
    out[item] = (s + b4[0]) * mask;
}

extern "C" void kernel_launch(void* const* d_in, const int* in_sizes, int n_in,
                              void* d_out, int out_size) {
    const float* x  = (const float*)d_in[0];
    const float* r  = (const float*)d_in[1];
    const float* W1 = (const float*)d_in[2];
    const float* b1 = (const float*)d_in[3];
    const float* W2 = (const float*)d_in[4];
    const float* b2 = (const float*)d_in[5];
    const float* W3 = (const float*)d_in[6];
    const float* b3 = (const float*)d_in[7];
    const float* W4 = (const float*)d_in[8];
    const float* b4 = (const float*)d_in[9];
    float* out = (float*)d_out;

    topk_kernel<<<NAG, T1>>>(x);
    transpose_kernel<<<1, 256>>>(W2, W3);
    feat_kernel<<<NITEMS / 256, 256>>>(x, r, W1, b1, out);
    gemm1_kernel<<<NITEMS / 128, 256>>>(b2);
    gemm2_kernel<<<NITEMS / 128, 128>>>(b3, W4, b4, out);
}